// round 11
// baseline (speedup 1.0000x reference)
#include <cuda_runtime.h>

#define NTREES 128
#define C 8
#define L 2
#define M 256
#define G 4
#define NTH 1024

typedef unsigned long long u64;

// ---------------- packed f32x2 helpers ----------------
static __device__ __forceinline__ u64 pk2f(float lo, float hi) {
    u64 r; asm("mov.b64 %0,{%1,%2};" : "=l"(r) : "f"(lo), "f"(hi)); return r;
}
static __device__ __forceinline__ void unpk2f(u64 v, float& lo, float& hi) {
    asm("mov.b64 {%0,%1},%2;" : "=f"(lo), "=f"(hi) : "l"(v));
}
static __device__ __forceinline__ u64 fma2p(u64 a, u64 b, u64 c) {
    u64 d; asm("fma.rn.f32x2 %0,%1,%2,%3;" : "=l"(d) : "l"(a), "l"(b), "l"(c)); return d;
}
static __device__ __forceinline__ u64 mul2p(u64 a, u64 b) {
    u64 d; asm("mul.rn.f32x2 %0,%1,%2;" : "=l"(d) : "l"(a), "l"(b)); return d;
}
static __device__ __forceinline__ u64 add2p(u64 a, u64 b) {
    u64 d; asm("add.rn.f32x2 %0,%1,%2;" : "=l"(d) : "l"(a), "l"(b)); return d;
}

// 8x8 matvec: A as ulonglong2 pairs over d; Ap pre-offset by (p*2 + gh).
static __device__ __forceinline__ void matvec8p(const ulonglong2* __restrict__ Ap,
                                                const u64* __restrict__ b,
                                                u64* __restrict__ o, bool acc) {
#pragma unroll
    for (int c = 0; c < 8; c++) {
        u64 mm = acc ? o[c] : 0ull;
#pragma unroll
        for (int d2 = 0; d2 < 4; d2++) {
            ulonglong2 a = Ap[(c * 4 + d2) * 4];
            mm = fma2p(a.x, b[2 * d2], mm);
            mm = fma2p(a.y, b[2 * d2 + 1], mm);
        }
        o[c] = mm;
    }
}

// ---------------- single fused kernel: one CTA per tree ----------------
// smem map (u64 units):
//   BmP   [0, 4096)      : ull2 [gh][c2][m]
//   A_s   [4096, 4352)   : ulonglong2[c][d2][p][gh]
//   TmsgP [4352, 12544)  : ull2 [gh][c2][pm]
//   Tlog  [12544, 13568) : [gh][pm]
//   Pi_s  [13568, 13600) : [p][c][gh]
//   l4buf [13600, 13856) : [gh][c][16]
//   red   [13856, 13858) : 4 floats
#define SMEM_U64 13858
#define SMEM_BYTES (SMEM_U64 * 8)

__global__ __launch_bounds__(NTH) void htmm_main(const float* __restrict__ lA,
                                                 const float* __restrict__ lB,
                                                 const float* __restrict__ lPi,
                                                 const float* __restrict__ lSP,
                                                 const int* __restrict__ pos,
                                                 const int* __restrict__ x,
                                                 float* __restrict__ out) {
    extern __shared__ u64 smu[];
    float* red = (float*)(smu + 13856);

    const int t = blockIdx.x, tid = threadIdx.x;
    const int gh = tid >> 9, nd = tid & 511;
    const int wid = tid >> 5, lane = tid & 31;

    // ========== per-CTA prologue 1: softmaxes into smem ==========
    // Bm: one warp per (c,g); lane handles 8 m's. Paired [gh][c2][m] layout.
    {
        int c = wid >> 2, g = wid & 3;
        float v[8];
        float mx = -1e30f;
#pragma unroll
        for (int j = 0; j < 8; j++) {
            v[j] = lB[(c * M + lane + 32 * j) * G + g];
            mx = fmaxf(mx, v[j]);
        }
#pragma unroll
        for (int o = 16; o; o >>= 1) mx = fmaxf(mx, __shfl_xor_sync(0xffffffffu, mx, o));
        float s = 0.f;
#pragma unroll
        for (int j = 0; j < 8; j++) { v[j] = __expf(v[j] - mx); s += v[j]; }
#pragma unroll
        for (int o = 16; o; o >>= 1) s += __shfl_xor_sync(0xffffffffu, s, o);
        float r = 1.f / s;
        float* BmF = (float*)smu;
        int ghw = g >> 1, gl = g & 1, c2 = c >> 1, cl = c & 1;
#pragma unroll
        for (int j = 0; j < 8; j++) {
            int m = lane + 32 * j;
            BmF[(((ghw * 4 + c2) * 256 + m) << 2) + cl * 2 + gl] = v[j] * r;
        }
    }
    // A softmax over c per (d,p,g), fold SP[p,g]  (64 threads)
    if (tid < 64) {
        int d = tid >> 3, p = (tid >> 2) & 1, g = tid & 3;
        float s0 = lSP[0 * G + g], s1 = lSP[1 * G + g];
        float mxs = fmaxf(s0, s1);
        float e0 = __expf(s0 - mxs), e1 = __expf(s1 - mxs);
        float sp = (p == 0 ? e0 : e1) / (e0 + e1);
        float mx = -1e30f;
#pragma unroll
        for (int c = 0; c < C; c++) mx = fmaxf(mx, lA[((c * C + d) * L + p) * G + g]);
        float s = 0.f;
#pragma unroll
        for (int c = 0; c < C; c++) s += __expf(lA[((c * C + d) * L + p) * G + g] - mx);
        float r = sp / s;
        float* AF = (float*)(smu + 4096);
        int d2 = d >> 1, dl = d & 1, ghx = g >> 1, gl = g & 1;
#pragma unroll
        for (int c = 0; c < C; c++) {
            int fi = ((((c * 4 + d2) * 2 + p) * 2 + ghx) * 2 + dl) * 2 + gl;
            AF[fi] = __expf(lA[((c * C + d) * L + p) * G + g] - mx) * r;
        }
    } else if (tid < 72) {
        int t2 = tid - 64;
        int p = t2 >> 2, g = t2 & 3;
        float mx = -1e30f;
#pragma unroll
        for (int c = 0; c < C; c++) mx = fmaxf(mx, lPi[(c * L + p) * G + g]);
        float s = 0.f;
#pragma unroll
        for (int c = 0; c < C; c++) s += __expf(lPi[(c * L + p) * G + g] - mx);
        float r = 1.f / s;
        float* PiF = (float*)(smu + 13568);  // idx p*32 + c*4 + g
#pragma unroll
        for (int c = 0; c < C; c++)
            PiF[p * 32 + c * 4 + g] = __expf(lPi[(c * L + p) * G + g] - mx) * r;
    }
    if (tid < 4) red[tid] = 0.f;
    __syncthreads();

    const ulonglong2* A2 = (const ulonglong2*)(smu + 4096);  // [(c*4+d2)*4 + p*2 + gh]

    // ========== per-CTA prologue 2: leaf table (thread = (pm, gh)) ==========
    {
        const int pm = tid & 511, ghb = tid >> 9;
        const int p = pm >> 8, m = pm & 255;
        const ulonglong2* BmPG = (const ulonglong2*)smu + ghb * 1024;
        u64 b[8], nu;
#pragma unroll
        for (int c2 = 0; c2 < 4; c2++) {
            ulonglong2 bm = BmPG[c2 * 256 + m];
            b[2 * c2]     = mul2p(smu[13568 + p * 16 + (2 * c2) * 2 + ghb], bm.x);
            b[2 * c2 + 1] = mul2p(smu[13568 + p * 16 + (2 * c2 + 1) * 2 + ghb], bm.y);
            u64 pr = add2p(b[2 * c2], b[2 * c2 + 1]);
            nu = (c2 == 0) ? pr : add2p(nu, pr);
        }
        float nx, ny; unpk2f(nu, nx, ny);
        smu[12544 + ghb * 512 + pm] = pk2f(__logf(nx), __logf(ny));
        u64 r = pk2f(__fdividef(1.f, nx), __fdividef(1.f, ny));
#pragma unroll
        for (int c = 0; c < 8; c++) b[c] = mul2p(b[c], r);
        u64 msg[8];
        matvec8p(A2 + p * 2 + ghb, b, msg, false);
        ulonglong2* TP = (ulonglong2*)(smu + 4352) + ghb * 2048;
#pragma unroll
        for (int c2 = 0; c2 < 4; c2++) {
            ulonglong2 w; w.x = msg[2 * c2]; w.y = msg[2 * c2 + 1];
            TP[c2 * 512 + pm] = w;
        }
    }
    __syncthreads();

    const ulonglong2* BmH2  = (const ulonglong2*)smu + gh * 1024;          // [c2*256+m]
    const ulonglong2* TmsgH = (const ulonglong2*)(smu + 4352) + gh * 2048; // [c2*512+pm]
    const u64* TlogH = smu + 12544 + gh * 512;
    const ulonglong2* A2h = A2 + gh;
    u64* l4b = smu + 13600 + gh * 128;   // [c*16 + w]

    float llx = 0.f, lly = 0.f;
    u64 cur[8];   // current message carried through shuffle levels

    // ---- fused levels 11 (table) -> 10 -> 9, all in registers ----
    {
        const int offL  = 128 * 2047 + (t << 11);
        const int off10 = 128 * 1023 + (t << 10);
        const int off9  = 128 * 511  + (t << 9);

        const int4 pL  = *(const int4*)(pos + offL + 4 * nd);
        const int4 xL  = *(const int4*)(x   + offL + 4 * nd);
        const int2 p10 = *(const int2*)(pos + off10 + 2 * nd);
        const int2 x10 = *(const int2*)(x   + off10 + 2 * nd);

        const int pm0 = pL.x * 256 + xL.x, pm1 = pL.y * 256 + xL.y;
        const int pm2 = pL.z * 256 + xL.z, pm3 = pL.w * 256 + xL.w;

        u64 llleaf = add2p(add2p(TlogH[pm0], TlogH[pm1]), add2p(TlogH[pm2], TlogH[pm3]));

        u64 acc9[8];
        u64 nuprodU = pk2f(1.f, 1.f);

#pragma unroll
        for (int s10 = 0; s10 < 2; s10++) {
            const int pma = (s10 == 0) ? pm0 : pm2;
            const int pmb = (s10 == 0) ? pm1 : pm3;
            int m = (s10 == 0) ? x10.x : x10.y;
            int p = (s10 == 0) ? p10.x : p10.y;

            u64 acc10[8];
            u64 nu;
#pragma unroll
            for (int c2 = 0; c2 < 4; c2++) {
                ulonglong2 ta = TmsgH[c2 * 512 + pma];
                ulonglong2 tb = TmsgH[c2 * 512 + pmb];
                ulonglong2 bm = BmH2[c2 * 256 + m];
                acc10[2 * c2]     = mul2p(add2p(ta.x, tb.x), bm.x);
                acc10[2 * c2 + 1] = mul2p(add2p(ta.y, tb.y), bm.y);
                u64 pr = add2p(acc10[2 * c2], acc10[2 * c2 + 1]);
                nu = (c2 == 0) ? pr : add2p(nu, pr);
            }
            nuprodU = mul2p(nuprodU, nu);
            float nx, ny; unpk2f(nu, nx, ny);
            u64 r = pk2f(__fdividef(1.f, nx), __fdividef(1.f, ny));
#pragma unroll
            for (int c = 0; c < 8; c++) acc10[c] = mul2p(acc10[c], r);
            matvec8p(A2h + p * 2, acc10, acc9, s10 != 0);
        }
        // level-9 node
        int m = x[off9 + nd];
        int p9 = pos[off9 + nd];
        u64 nu;
#pragma unroll
        for (int c2 = 0; c2 < 4; c2++) {
            ulonglong2 bm = BmH2[c2 * 256 + m];
            acc9[2 * c2]     = mul2p(acc9[2 * c2], bm.x);
            acc9[2 * c2 + 1] = mul2p(acc9[2 * c2 + 1], bm.y);
            u64 pr = add2p(acc9[2 * c2], acc9[2 * c2 + 1]);
            nu = (c2 == 0) ? pr : add2p(nu, pr);
        }
        nuprodU = mul2p(nuprodU, nu);
        float nx, ny; unpk2f(nu, nx, ny);
        u64 r = pk2f(__fdividef(1.f, nx), __fdividef(1.f, ny));
#pragma unroll
        for (int c = 0; c < 8; c++) acc9[c] = mul2p(acc9[c], r);
        matvec8p(A2h + p9 * 2, acc9, cur, false);   // l9 message stays in registers

        float ax, ay, bx, by;
        unpk2f(llleaf, ax, ay);
        unpk2f(nuprodU, bx, by);
        llx += ax + __logf(bx);
        lly += ay + __logf(by);
    }

    // ---- levels 8..4 via warp shuffles (32 l9 msgs per warp = one l4 subtree) ----
    {
        float prodx = 1.f, prody = 1.f;
#pragma unroll
        for (int lam = 8; lam >= 4; --lam) {
            const int sh = 9 - lam;           // 1..5
            u64 sib[8];
#pragma unroll
            for (int c = 0; c < 8; c++)
                sib[c] = __shfl_xor_sync(0xffffffffu, cur[c], 1 << (sh - 1));
            if ((nd & ((1 << sh) - 1)) == 0) {
                const int node = nd >> sh;
                const int off = 128 * ((1 << lam) - 1) + (t << lam);
                int m = x[off + node];
                int p = pos[off + node];
                u64 v[8]; u64 nu;
#pragma unroll
                for (int c2 = 0; c2 < 4; c2++) {
                    ulonglong2 bm = BmH2[c2 * 256 + m];
                    v[2 * c2]     = mul2p(add2p(cur[2 * c2],     sib[2 * c2]),     bm.x);
                    v[2 * c2 + 1] = mul2p(add2p(cur[2 * c2 + 1], sib[2 * c2 + 1]), bm.y);
                    u64 pr = add2p(v[2 * c2], v[2 * c2 + 1]);
                    nu = (c2 == 0) ? pr : add2p(nu, pr);
                }
                float nx, ny; unpk2f(nu, nx, ny);
                prodx *= nx; prody *= ny;
                u64 r = pk2f(__fdividef(1.f, nx), __fdividef(1.f, ny));
#pragma unroll
                for (int c = 0; c < 8; c++) v[c] = mul2p(v[c], r);
                matvec8p(A2h + p * 2, v, cur, false);
            }
        }
        llx += __logf(prodx);
        lly += __logf(prody);
        if ((nd & 31) == 0) {
            const int w = nd >> 5;   // 0..15
#pragma unroll
            for (int c = 0; c < 8; c++) l4b[c * 16 + w] = cur[c];
        }
    }
    __syncthreads();

    // ---- tail: levels 3..0 in one warp per gh (lanes = l4 nodes) ----
    if (nd < 32) {
        u64 cur2[8];
#pragma unroll
        for (int c = 0; c < 8; c++) cur2[c] = 0ull;
        if (nd < 16) {
#pragma unroll
            for (int c = 0; c < 8; c++) cur2[c] = l4b[c * 16 + nd];
        }
        float prodx = 1.f, prody = 1.f;
#pragma unroll
        for (int lam = 3; lam >= 0; --lam) {
            const int sh = 4 - lam;           // 1..4
            u64 sib[8];
#pragma unroll
            for (int c = 0; c < 8; c++)
                sib[c] = __shfl_xor_sync(0xffffffffu, cur2[c], 1 << (sh - 1));
            if (nd < 16 && (nd & ((1 << sh) - 1)) == 0) {
                const int node = nd >> sh;
                const int off = 128 * ((1 << lam) - 1) + (t << lam);
                int m = x[off + node];
                u64 v[8]; u64 nu;
#pragma unroll
                for (int c2 = 0; c2 < 4; c2++) {
                    ulonglong2 bm = BmH2[c2 * 256 + m];
                    v[2 * c2]     = mul2p(add2p(cur2[2 * c2],     sib[2 * c2]),     bm.x);
                    v[2 * c2 + 1] = mul2p(add2p(cur2[2 * c2 + 1], sib[2 * c2 + 1]), bm.y);
                    u64 pr = add2p(v[2 * c2], v[2 * c2 + 1]);
                    nu = (c2 == 0) ? pr : add2p(nu, pr);
                }
                float nx, ny; unpk2f(nu, nx, ny);
                prodx *= nx; prody *= ny;
                if (lam > 0) {
                    int p = pos[off + node];
                    u64 r = pk2f(__fdividef(1.f, nx), __fdividef(1.f, ny));
#pragma unroll
                    for (int c = 0; c < 8; c++) v[c] = mul2p(v[c], r);
                    matvec8p(A2h + p * 2, v, cur2, false);
                }
            }
        }
        llx += __logf(prodx);
        lly += __logf(prody);
    }

    // ---- reduction ----
#pragma unroll
    for (int o = 16; o; o >>= 1) {
        llx += __shfl_xor_sync(0xffffffffu, llx, o);
        lly += __shfl_xor_sync(0xffffffffu, lly, o);
    }
    if ((tid & 31) == 0) {
        atomicAdd(&red[2 * gh + 0], llx);
        atomicAdd(&red[2 * gh + 1], lly);
    }
    __syncthreads();
    if (tid < 4) out[t * 4 + tid] = red[tid];
}

extern "C" void kernel_launch(void* const* d_in, const int* in_sizes, int n_in,
                              void* d_out, int out_size) {
    const float* lA  = (const float*)d_in[0];
    const float* lB  = (const float*)d_in[1];
    const float* lPi = (const float*)d_in[2];
    const float* lSP = (const float*)d_in[3];
    const int*   pos = (const int*)d_in[4];
    const int*   x   = (const int*)d_in[5];
    float*       out = (float*)d_out;

    cudaFuncSetAttribute(htmm_main, cudaFuncAttributeMaxDynamicSharedMemorySize, SMEM_BYTES);

    htmm_main<<<NTREES, NTH, SMEM_BYTES>>>(lA, lB, lPi, lSP, pos, x, out);
}

// round 12
// speedup vs baseline: 1.0725x; 1.0725x over previous
#include <cuda_runtime.h>

#define NTREES 128
#define C 8
#define L 2
#define M 256
#define G 4
#define NTH 1024

typedef unsigned long long u64;

// ---------------- packed f32x2 helpers ----------------
static __device__ __forceinline__ u64 pk2f(float lo, float hi) {
    u64 r; asm("mov.b64 %0,{%1,%2};" : "=l"(r) : "f"(lo), "f"(hi)); return r;
}
static __device__ __forceinline__ void unpk2f(u64 v, float& lo, float& hi) {
    asm("mov.b64 {%0,%1},%2;" : "=f"(lo), "=f"(hi) : "l"(v));
}
static __device__ __forceinline__ u64 fma2p(u64 a, u64 b, u64 c) {
    u64 d; asm("fma.rn.f32x2 %0,%1,%2,%3;" : "=l"(d) : "l"(a), "l"(b), "l"(c)); return d;
}
static __device__ __forceinline__ u64 mul2p(u64 a, u64 b) {
    u64 d; asm("mul.rn.f32x2 %0,%1,%2;" : "=l"(d) : "l"(a), "l"(b)); return d;
}
static __device__ __forceinline__ u64 add2p(u64 a, u64 b) {
    u64 d; asm("add.rn.f32x2 %0,%1,%2;" : "=l"(d) : "l"(a), "l"(b)); return d;
}

// 8x8 matvec on UNNORMALIZED b with output scaling by r:
//   o[c] = (A@b)[c] * r        (acc=false)
//   o[c] += (A@b)[c] * r       (acc=true)
// The caller's nu/rcp computation overlaps with the matvec (A@(b*r) == (A@b)*r).
static __device__ __forceinline__ void matvec8ps(const ulonglong2* __restrict__ Ap,
                                                 const u64* __restrict__ b, u64 r,
                                                 u64* __restrict__ o, bool acc) {
#pragma unroll
    for (int c = 0; c < 8; c++) {
        u64 mm = 0ull;
#pragma unroll
        for (int d2 = 0; d2 < 4; d2++) {
            ulonglong2 a = Ap[(c * 4 + d2) * 4];
            mm = fma2p(a.x, b[2 * d2], mm);
            mm = fma2p(a.y, b[2 * d2 + 1], mm);
        }
        o[c] = acc ? fma2p(mm, r, o[c]) : mul2p(mm, r);
    }
}

// ---------------- single fused kernel: one CTA per tree ----------------
// smem map (u64 units):
//   bufA [0, 8192)       : [gh][c][512]  (levels 9,7,5,3,1)
//   bufB [8192, 12288)   : [gh][c][256]  (levels 8,6,4,2)
//   BmP  [12288, 16384)  : ull2 [gh][c2][m]
//   A_s  [16384, 16640)  : ulonglong2[c][d2][p][gh]
//   TmsgP[16640, 24832)  : ull2 [gh][c2][pm]
//   Tlog [24832, 25856)  : [gh][pm]
//   Pi_s [25856, 25888)  : [p][c][gh]
//   red  [25888, 25890)  : 4 floats
#define SMEM_U64 25890
#define SMEM_BYTES (SMEM_U64 * 8)

__global__ __launch_bounds__(NTH) void htmm_main(const float* __restrict__ lA,
                                                 const float* __restrict__ lB,
                                                 const float* __restrict__ lPi,
                                                 const float* __restrict__ lSP,
                                                 const int* __restrict__ pos,
                                                 const int* __restrict__ x,
                                                 float* __restrict__ out) {
    extern __shared__ u64 smu[];
    float* red = (float*)(smu + 25888);

    const int t = blockIdx.x, tid = threadIdx.x;
    const int gh = tid >> 9, nd = tid & 511;
    const int wid = tid >> 5, lane = tid & 31;

    // ========== per-CTA prologue 1: softmaxes into smem ==========
    {
        int c = wid >> 2, g = wid & 3;
        float v[8];
        float mx = -1e30f;
#pragma unroll
        for (int j = 0; j < 8; j++) {
            v[j] = lB[(c * M + lane + 32 * j) * G + g];
            mx = fmaxf(mx, v[j]);
        }
#pragma unroll
        for (int o = 16; o; o >>= 1) mx = fmaxf(mx, __shfl_xor_sync(0xffffffffu, mx, o));
        float s = 0.f;
#pragma unroll
        for (int j = 0; j < 8; j++) { v[j] = __expf(v[j] - mx); s += v[j]; }
#pragma unroll
        for (int o = 16; o; o >>= 1) s += __shfl_xor_sync(0xffffffffu, s, o);
        float r = 1.f / s;
        float* BmF = (float*)(smu + 12288);
        int ghw = g >> 1, gl = g & 1, c2 = c >> 1, cl = c & 1;
#pragma unroll
        for (int j = 0; j < 8; j++) {
            int m = lane + 32 * j;
            BmF[(((ghw * 4 + c2) * 256 + m) << 2) + cl * 2 + gl] = v[j] * r;
        }
    }
    if (tid < 64) {
        int d = tid >> 3, p = (tid >> 2) & 1, g = tid & 3;
        float s0 = lSP[0 * G + g], s1 = lSP[1 * G + g];
        float mxs = fmaxf(s0, s1);
        float e0 = __expf(s0 - mxs), e1 = __expf(s1 - mxs);
        float sp = (p == 0 ? e0 : e1) / (e0 + e1);
        float mx = -1e30f;
#pragma unroll
        for (int c = 0; c < C; c++) mx = fmaxf(mx, lA[((c * C + d) * L + p) * G + g]);
        float s = 0.f;
#pragma unroll
        for (int c = 0; c < C; c++) s += __expf(lA[((c * C + d) * L + p) * G + g] - mx);
        float r = sp / s;
        float* AF = (float*)(smu + 16384);
        int d2 = d >> 1, dl = d & 1, ghx = g >> 1, gl = g & 1;
#pragma unroll
        for (int c = 0; c < C; c++) {
            int fi = ((((c * 4 + d2) * 2 + p) * 2 + ghx) * 2 + dl) * 2 + gl;
            AF[fi] = __expf(lA[((c * C + d) * L + p) * G + g] - mx) * r;
        }
    } else if (tid < 72) {
        int t2 = tid - 64;
        int p = t2 >> 2, g = t2 & 3;
        float mx = -1e30f;
#pragma unroll
        for (int c = 0; c < C; c++) mx = fmaxf(mx, lPi[(c * L + p) * G + g]);
        float s = 0.f;
#pragma unroll
        for (int c = 0; c < C; c++) s += __expf(lPi[(c * L + p) * G + g] - mx);
        float r = 1.f / s;
        float* PiF = (float*)(smu + 25856);  // idx p*32 + c*4 + g
#pragma unroll
        for (int c = 0; c < C; c++)
            PiF[p * 32 + c * 4 + g] = __expf(lPi[(c * L + p) * G + g] - mx) * r;
    }
    if (tid < 4) red[tid] = 0.f;
    __syncthreads();

    const ulonglong2* A2 = (const ulonglong2*)(smu + 16384);  // [(c*4+d2)*4 + p*2 + gh]

    // ========== per-CTA prologue 2: leaf table (thread = (pm, gh)) ==========
    {
        const int pm = tid & 511, ghb = tid >> 9;
        const int p = pm >> 8, m = pm & 255;
        const ulonglong2* BmPG = (const ulonglong2*)(smu + 12288) + ghb * 1024;
        u64 b[8], nu;
#pragma unroll
        for (int c2 = 0; c2 < 4; c2++) {
            ulonglong2 bm = BmPG[c2 * 256 + m];
            b[2 * c2]     = mul2p(smu[25856 + p * 16 + (2 * c2) * 2 + ghb], bm.x);
            b[2 * c2 + 1] = mul2p(smu[25856 + p * 16 + (2 * c2 + 1) * 2 + ghb], bm.y);
            u64 pr = add2p(b[2 * c2], b[2 * c2 + 1]);
            nu = (c2 == 0) ? pr : add2p(nu, pr);
        }
        float nx, ny; unpk2f(nu, nx, ny);
        smu[24832 + ghb * 512 + pm] = pk2f(__logf(nx), __logf(ny));
        u64 r = pk2f(__fdividef(1.f, nx), __fdividef(1.f, ny));
        u64 msg[8];
        matvec8ps(A2 + p * 2 + ghb, b, r, msg, false);
        ulonglong2* TP = (ulonglong2*)(smu + 16640) + ghb * 2048;
#pragma unroll
        for (int c2 = 0; c2 < 4; c2++) {
            ulonglong2 w; w.x = msg[2 * c2]; w.y = msg[2 * c2 + 1];
            TP[c2 * 512 + pm] = w;
        }
    }
    __syncthreads();

    const ulonglong2* BmH2  = (const ulonglong2*)(smu + 12288) + gh * 1024; // [c2*256+m]
    const ulonglong2* TmsgH = (const ulonglong2*)(smu + 16640) + gh * 2048; // [c2*512+pm]
    const u64* TlogH = smu + 24832 + gh * 512;
    const ulonglong2* A2h = A2 + gh;
    u64* bufAh = smu + gh * 4096;
    u64* bufBh = smu + 8192 + gh * 2048;

    float llx = 0.f, lly = 0.f;

    // ---- fused levels 11 (table lookup) -> 10 -> 9 in registers ----
    {
        const int offL  = 128 * 2047 + (t << 11);
        const int off10 = 128 * 1023 + (t << 10);
        const int off9  = 128 * 511  + (t << 9);

        const int4 pL  = *(const int4*)(pos + offL + 4 * nd);
        const int4 xL  = *(const int4*)(x   + offL + 4 * nd);
        const int2 p10 = *(const int2*)(pos + off10 + 2 * nd);
        const int2 x10 = *(const int2*)(x   + off10 + 2 * nd);

        const int pm0 = pL.x * 256 + xL.x, pm1 = pL.y * 256 + xL.y;
        const int pm2 = pL.z * 256 + xL.z, pm3 = pL.w * 256 + xL.w;

        u64 llleaf = add2p(add2p(TlogH[pm0], TlogH[pm1]), add2p(TlogH[pm2], TlogH[pm3]));

        u64 acc9[8];
        u64 nuprodU = pk2f(1.f, 1.f);

#pragma unroll
        for (int s10 = 0; s10 < 2; s10++) {
            const int pma = (s10 == 0) ? pm0 : pm2;
            const int pmb = (s10 == 0) ? pm1 : pm3;
            int m = (s10 == 0) ? x10.x : x10.y;
            int p = (s10 == 0) ? p10.x : p10.y;

            u64 acc10[8];
            u64 nu;
#pragma unroll
            for (int c2 = 0; c2 < 4; c2++) {
                ulonglong2 ta = TmsgH[c2 * 512 + pma];
                ulonglong2 tb = TmsgH[c2 * 512 + pmb];
                ulonglong2 bm = BmH2[c2 * 256 + m];
                acc10[2 * c2]     = mul2p(add2p(ta.x, tb.x), bm.x);
                acc10[2 * c2 + 1] = mul2p(add2p(ta.y, tb.y), bm.y);
                u64 pr = add2p(acc10[2 * c2], acc10[2 * c2 + 1]);
                nu = (c2 == 0) ? pr : add2p(nu, pr);
            }
            nuprodU = mul2p(nuprodU, nu);
            float nx, ny; unpk2f(nu, nx, ny);
            u64 r = pk2f(__fdividef(1.f, nx), __fdividef(1.f, ny));
            // matvec on unnormalized acc10, r folded into accumulate
            matvec8ps(A2h + p * 2, acc10, r, acc9, s10 != 0);
        }
        // level-9 node
        int m = x[off9 + nd];
        int p9 = pos[off9 + nd];
        u64 nu;
#pragma unroll
        for (int c2 = 0; c2 < 4; c2++) {
            ulonglong2 bm = BmH2[c2 * 256 + m];
            acc9[2 * c2]     = mul2p(acc9[2 * c2], bm.x);
            acc9[2 * c2 + 1] = mul2p(acc9[2 * c2 + 1], bm.y);
            u64 pr = add2p(acc9[2 * c2], acc9[2 * c2 + 1]);
            nu = (c2 == 0) ? pr : add2p(nu, pr);
        }
        nuprodU = mul2p(nuprodU, nu);
        float nx, ny; unpk2f(nu, nx, ny);
        u64 r = pk2f(__fdividef(1.f, nx), __fdividef(1.f, ny));
        u64 msg[8];
        matvec8ps(A2h + p9 * 2, acc9, r, msg, false);
#pragma unroll
        for (int c = 0; c < 8; c++) bufAh[c * 512 + nd] = msg[c];

        float ax, ay, bx, by;
        unpk2f(llleaf, ax, ay);
        unpk2f(nuprodU, bx, by);
        llx += ax + __logf(bx);
        lly += ay + __logf(by);
    }
    __syncthreads();

    // ---- single-phase levels: l = child level (9,8,7); logs batched ----
    {
        float prodx = 1.f, prody = 1.f;
#pragma unroll 1
        for (int l = 9; l >= 7; --l) {
            const int n_pa = 1 << (l - 1);            // 256, 128, 64
            u64* chb = (l & 1) ? bufAh : bufBh;
            const int csh = (l & 1) ? 256 : 128;
            u64* pb  = (l & 1) ? bufBh : bufAh;
            const int ps = (l & 1) ? 256 : 512;
            const int offP = 128 * ((1 << (l - 1)) - 1) + (t << (l - 1));

            if (nd < n_pa) {
                const int pa = nd;
                int m = x[offP + pa];
                int p = pos[offP + pa];
                const ulonglong2* ch2 = (const ulonglong2*)chb;
                u64 v[8];
                u64 nu;
#pragma unroll
                for (int c2 = 0; c2 < 4; c2++) {
                    ulonglong2 prA = ch2[(2 * c2) * csh + pa];
                    ulonglong2 prB = ch2[(2 * c2 + 1) * csh + pa];
                    ulonglong2 bm = BmH2[c2 * 256 + m];
                    v[2 * c2]     = mul2p(add2p(prA.x, prA.y), bm.x);
                    v[2 * c2 + 1] = mul2p(add2p(prB.x, prB.y), bm.y);
                    u64 pr = add2p(v[2 * c2], v[2 * c2 + 1]);
                    nu = (c2 == 0) ? pr : add2p(nu, pr);
                }
                float nx, ny; unpk2f(nu, nx, ny);
                prodx *= nx; prody *= ny;
                u64 r = pk2f(__fdividef(1.f, nx), __fdividef(1.f, ny));
                u64 msg[8];
                matvec8ps(A2h + p * 2, v, r, msg, false);
#pragma unroll
                for (int c = 0; c < 8; c++) pb[c * ps + pa] = msg[c];
            }
            __syncthreads();
        }
        if (nd < 256) {
            llx += __logf(prodx);
            lly += __logf(prody);
        }
    }

    // ---- tail: l = 6..1, two independent warps (one per gh) ----
    if (nd < 32) {
        float prodx = 1.f, prody = 1.f;
#pragma unroll 1
        for (int l = 6; l >= 1; --l) {
            const int n_pa = 1 << (l - 1);
            u64* chb = (l & 1) ? bufAh : bufBh;
            const int csh = (l & 1) ? 256 : 128;
            u64* pb  = (l & 1) ? bufBh : bufAh;
            const int ps = (l & 1) ? 256 : 512;
            const int offP = 128 * ((1 << (l - 1)) - 1) + (t << (l - 1));

            if (nd < n_pa) {
                const int pa = nd;
                int m = x[offP + pa];
                const ulonglong2* ch2 = (const ulonglong2*)chb;
                u64 v[8];
                u64 nu;
#pragma unroll
                for (int c2 = 0; c2 < 4; c2++) {
                    ulonglong2 prA = ch2[(2 * c2) * csh + pa];
                    ulonglong2 prB = ch2[(2 * c2 + 1) * csh + pa];
                    ulonglong2 bm = BmH2[c2 * 256 + m];
                    v[2 * c2]     = mul2p(add2p(prA.x, prA.y), bm.x);
                    v[2 * c2 + 1] = mul2p(add2p(prB.x, prB.y), bm.y);
                    u64 pr = add2p(v[2 * c2], v[2 * c2 + 1]);
                    nu = (c2 == 0) ? pr : add2p(nu, pr);
                }
                float nx, ny; unpk2f(nu, nx, ny);
                prodx *= nx; prody *= ny;
                if (l > 1) {
                    int p = pos[offP + pa];
                    u64 r = pk2f(__fdividef(1.f, nx), __fdividef(1.f, ny));
                    u64 msg[8];
                    matvec8ps(A2h + p * 2, v, r, msg, false);
#pragma unroll
                    for (int c = 0; c < 8; c++) pb[c * ps + pa] = msg[c];
                }
            }
            __syncwarp();
        }
        llx += __logf(prodx);
        lly += __logf(prody);
    }

    // ---- reduction ----
#pragma unroll
    for (int o = 16; o; o >>= 1) {
        llx += __shfl_xor_sync(0xffffffffu, llx, o);
        lly += __shfl_xor_sync(0xffffffffu, lly, o);
    }
    if ((tid & 31) == 0) {
        atomicAdd(&red[2 * gh + 0], llx);
        atomicAdd(&red[2 * gh + 1], lly);
    }
    __syncthreads();
    if (tid < 4) out[t * 4 + tid] = red[tid];
}

extern "C" void kernel_launch(void* const* d_in, const int* in_sizes, int n_in,
                              void* d_out, int out_size) {
    const float* lA  = (const float*)d_in[0];
    const float* lB  = (const float*)d_in[1];
    const float* lPi = (const float*)d_in[2];
    const float* lSP = (const float*)d_in[3];
    const int*   pos = (const int*)d_in[4];
    const int*   x   = (const int*)d_in[5];
    float*       out = (float*)d_out;

    cudaFuncSetAttribute(htmm_main, cudaFuncAttributeMaxDynamicSharedMemorySize, SMEM_BYTES);

    htmm_main<<<NTREES, NTH, SMEM_BYTES>>>(lA, lB, lPi, lSP, pos, x, out);
}

// round 14
// speedup vs baseline: 1.1415x; 1.0643x over previous
#include <cuda_runtime.h>

#define NTREES 128
#define C 8
#define L 2
#define M 256
#define G 4
#define NTH 1024

typedef unsigned long long u64;

// ---------------- packed f32x2 helpers ----------------
static __device__ __forceinline__ u64 pk2f(float lo, float hi) {
    u64 r; asm("mov.b64 %0,{%1,%2};" : "=l"(r) : "f"(lo), "f"(hi)); return r;
}
static __device__ __forceinline__ void unpk2f(u64 v, float& lo, float& hi) {
    asm("mov.b64 {%0,%1},%2;" : "=f"(lo), "=f"(hi) : "l"(v));
}
static __device__ __forceinline__ u64 fma2p(u64 a, u64 b, u64 c) {
    u64 d; asm("fma.rn.f32x2 %0,%1,%2,%3;" : "=l"(d) : "l"(a), "l"(b), "l"(c)); return d;
}
static __device__ __forceinline__ u64 mul2p(u64 a, u64 b) {
    u64 d; asm("mul.rn.f32x2 %0,%1,%2;" : "=l"(d) : "l"(a), "l"(b)); return d;
}
static __device__ __forceinline__ u64 add2p(u64 a, u64 b) {
    u64 d; asm("add.rn.f32x2 %0,%1,%2;" : "=l"(d) : "l"(a), "l"(b)); return d;
}

// 8x8 matvec: A as ulonglong2 pairs over d; Ap pre-offset by (p*2 + gh).
static __device__ __forceinline__ void matvec8p(const ulonglong2* __restrict__ Ap,
                                                const u64* __restrict__ b,
                                                u64* __restrict__ o, bool acc) {
#pragma unroll
    for (int c = 0; c < 8; c++) {
        u64 mm = acc ? o[c] : 0ull;
#pragma unroll
        for (int d2 = 0; d2 < 4; d2++) {
            ulonglong2 a = Ap[(c * 4 + d2) * 4];
            mm = fma2p(a.x, b[2 * d2], mm);
            mm = fma2p(a.y, b[2 * d2 + 1], mm);
        }
        o[c] = mm;
    }
}

// ---------------- single fused kernel: one CTA per tree ----------------
// smem map (u64 units):
//   bufA [0, 8192)       : [gh][c][512]  (levels 9,7,5,3,1)
//   bufB [8192, 12288)   : [gh][c][256]  (levels 8,6,4,2)
//   BmP  [12288, 16384)  : ull2 [gh][c2][m]
//   A_s  [16384, 16640)  : ulonglong2[c][d2][p][gh]
//   TmsgP[16640, 24832)  : ull2 [gh][c2][pm]
//   Tlog [24832, 25856)  : [gh][pm]
//   Pi_s [25856, 25888)  : [p][c][gh]
//   red  [25888, 25890)  : 4 floats
//   xs   [25890, 26402)  : 1024 ints (= 512 u64)  x for levels 0..9, heap order
//   ps   [26402, 26914)  : 1024 ints (= 512 u64)  pos, same order
#define SMEM_U64 26914
#define SMEM_BYTES (SMEM_U64 * 8)

__global__ __launch_bounds__(NTH) void htmm_main(const float* __restrict__ lA,
                                                 const float* __restrict__ lB,
                                                 const float* __restrict__ lPi,
                                                 const float* __restrict__ lSP,
                                                 const int* __restrict__ pos,
                                                 const int* __restrict__ x,
                                                 float* __restrict__ out) {
    extern __shared__ u64 smu[];
    float* red = (float*)(smu + 25888);
    int* xs = (int*)(smu + 25890);
    int* ps = (int*)(smu + 26402);

    const int t = blockIdx.x, tid = threadIdx.x;
    const int gh = tid >> 9, nd = tid & 511;
    const int wid = tid >> 5, lane = tid & 31;

    // ========== prefetch x/pos for levels 0..9 into smem (heap order) ==========
    // i in [0,1023): level l = ilog2(i+1), node j = i+1-2^l.
    if (tid < 1023) {
        int ip1 = tid + 1;
        int l = 31 - __clz(ip1);
        int j = ip1 - (1 << l);
        int gidx = 128 * ((1 << l) - 1) + (t << l) + j;
        xs[tid] = x[gidx];
        ps[tid] = pos[gidx];
    }

    // ========== per-CTA prologue 1: softmaxes into smem ==========
    {
        int c = wid >> 2, g = wid & 3;
        float v[8];
        float mx = -1e30f;
#pragma unroll
        for (int j = 0; j < 8; j++) {
            v[j] = lB[(c * M + lane + 32 * j) * G + g];
            mx = fmaxf(mx, v[j]);
        }
#pragma unroll
        for (int o = 16; o; o >>= 1) mx = fmaxf(mx, __shfl_xor_sync(0xffffffffu, mx, o));
        float s = 0.f;
#pragma unroll
        for (int j = 0; j < 8; j++) { v[j] = __expf(v[j] - mx); s += v[j]; }
#pragma unroll
        for (int o = 16; o; o >>= 1) s += __shfl_xor_sync(0xffffffffu, s, o);
        float r = 1.f / s;
        float* BmF = (float*)(smu + 12288);
        int ghw = g >> 1, gl = g & 1, c2 = c >> 1, cl = c & 1;
#pragma unroll
        for (int j = 0; j < 8; j++) {
            int m = lane + 32 * j;
            BmF[(((ghw * 4 + c2) * 256 + m) << 2) + cl * 2 + gl] = v[j] * r;
        }
    }
    if (tid < 64) {
        int d = tid >> 3, p = (tid >> 2) & 1, g = tid & 3;
        float s0 = lSP[0 * G + g], s1 = lSP[1 * G + g];
        float mxs = fmaxf(s0, s1);
        float e0 = __expf(s0 - mxs), e1 = __expf(s1 - mxs);
        float sp = (p == 0 ? e0 : e1) / (e0 + e1);
        float mx = -1e30f;
#pragma unroll
        for (int c = 0; c < C; c++) mx = fmaxf(mx, lA[((c * C + d) * L + p) * G + g]);
        float s = 0.f;
#pragma unroll
        for (int c = 0; c < C; c++) s += __expf(lA[((c * C + d) * L + p) * G + g] - mx);
        float r = sp / s;
        float* AF = (float*)(smu + 16384);
        int d2 = d >> 1, dl = d & 1, ghx = g >> 1, gl = g & 1;
#pragma unroll
        for (int c = 0; c < C; c++) {
            int fi = ((((c * 4 + d2) * 2 + p) * 2 + ghx) * 2 + dl) * 2 + gl;
            AF[fi] = __expf(lA[((c * C + d) * L + p) * G + g] - mx) * r;
        }
    } else if (tid < 72) {
        int t2 = tid - 64;
        int p = t2 >> 2, g = t2 & 3;
        float mx = -1e30f;
#pragma unroll
        for (int c = 0; c < C; c++) mx = fmaxf(mx, lPi[(c * L + p) * G + g]);
        float s = 0.f;
#pragma unroll
        for (int c = 0; c < C; c++) s += __expf(lPi[(c * L + p) * G + g] - mx);
        float r = 1.f / s;
        float* PiF = (float*)(smu + 25856);  // idx p*32 + c*4 + g
#pragma unroll
        for (int c = 0; c < C; c++)
            PiF[p * 32 + c * 4 + g] = __expf(lPi[(c * L + p) * G + g] - mx) * r;
    }
    if (tid < 4) red[tid] = 0.f;
    __syncthreads();

    const ulonglong2* A2 = (const ulonglong2*)(smu + 16384);  // [(c*4+d2)*4 + p*2 + gh]

    // ========== per-CTA prologue 2: leaf table (thread = (pm, gh)) ==========
    {
        const int pm = tid & 511, ghb = tid >> 9;
        const int p = pm >> 8, m = pm & 255;
        const ulonglong2* BmPG = (const ulonglong2*)(smu + 12288) + ghb * 1024;
        u64 b[8], nu;
#pragma unroll
        for (int c2 = 0; c2 < 4; c2++) {
            ulonglong2 bm = BmPG[c2 * 256 + m];
            b[2 * c2]     = mul2p(smu[25856 + p * 16 + (2 * c2) * 2 + ghb], bm.x);
            b[2 * c2 + 1] = mul2p(smu[25856 + p * 16 + (2 * c2 + 1) * 2 + ghb], bm.y);
            u64 pr = add2p(b[2 * c2], b[2 * c2 + 1]);
            nu = (c2 == 0) ? pr : add2p(nu, pr);
        }
        float nx, ny; unpk2f(nu, nx, ny);
        smu[24832 + ghb * 512 + pm] = pk2f(__logf(nx), __logf(ny));
        u64 r = pk2f(__fdividef(1.f, nx), __fdividef(1.f, ny));
#pragma unroll
        for (int c = 0; c < 8; c++) b[c] = mul2p(b[c], r);
        u64 msg[8];
        matvec8p(A2 + p * 2 + ghb, b, msg, false);
        ulonglong2* TP = (ulonglong2*)(smu + 16640) + ghb * 2048;
#pragma unroll
        for (int c2 = 0; c2 < 4; c2++) {
            ulonglong2 w; w.x = msg[2 * c2]; w.y = msg[2 * c2 + 1];
            TP[c2 * 512 + pm] = w;
        }
    }
    __syncthreads();

    const ulonglong2* BmH2  = (const ulonglong2*)(smu + 12288) + gh * 1024; // [c2*256+m]
    const ulonglong2* TmsgH = (const ulonglong2*)(smu + 16640) + gh * 2048; // [c2*512+pm]
    const u64* TlogH = smu + 24832 + gh * 512;
    const ulonglong2* A2h = A2 + gh;
    u64* bufAh = smu + gh * 4096;
    u64* bufBh = smu + 8192 + gh * 2048;

    float llx = 0.f, lly = 0.f;

    // ---- fused levels 11 (table lookup) -> 10 -> 9 in registers ----
    {
        const int offL  = 128 * 2047 + (t << 11);
        const int off10 = 128 * 1023 + (t << 10);

        const int4 pL  = *(const int4*)(pos + offL + 4 * nd);
        const int4 xL  = *(const int4*)(x   + offL + 4 * nd);
        const int2 p10 = *(const int2*)(pos + off10 + 2 * nd);
        const int2 x10 = *(const int2*)(x   + off10 + 2 * nd);

        const int pm0 = pL.x * 256 + xL.x, pm1 = pL.y * 256 + xL.y;
        const int pm2 = pL.z * 256 + xL.z, pm3 = pL.w * 256 + xL.w;

        u64 llleaf = add2p(add2p(TlogH[pm0], TlogH[pm1]), add2p(TlogH[pm2], TlogH[pm3]));

        u64 acc9[8];
        u64 nuprodU = pk2f(1.f, 1.f);

#pragma unroll
        for (int s10 = 0; s10 < 2; s10++) {
            const int pma = (s10 == 0) ? pm0 : pm2;
            const int pmb = (s10 == 0) ? pm1 : pm3;
            int m = (s10 == 0) ? x10.x : x10.y;
            int p = (s10 == 0) ? p10.x : p10.y;

            u64 acc10[8];
            u64 nu;
#pragma unroll
            for (int c2 = 0; c2 < 4; c2++) {
                ulonglong2 ta = TmsgH[c2 * 512 + pma];
                ulonglong2 tb = TmsgH[c2 * 512 + pmb];
                ulonglong2 bm = BmH2[c2 * 256 + m];
                acc10[2 * c2]     = mul2p(add2p(ta.x, tb.x), bm.x);
                acc10[2 * c2 + 1] = mul2p(add2p(ta.y, tb.y), bm.y);
                u64 pr = add2p(acc10[2 * c2], acc10[2 * c2 + 1]);
                nu = (c2 == 0) ? pr : add2p(nu, pr);
            }
            nuprodU = mul2p(nuprodU, nu);
            float nx, ny; unpk2f(nu, nx, ny);
            u64 r = pk2f(__fdividef(1.f, nx), __fdividef(1.f, ny));
#pragma unroll
            for (int c = 0; c < 8; c++) acc10[c] = mul2p(acc10[c], r);
            matvec8p(A2h + p * 2, acc10, acc9, s10 != 0);
        }
        // level-9 node (x/pos from prefetched smem: heap index 511+nd)
        int m = xs[511 + nd];
        int p9 = ps[511 + nd];
        u64 nu;
#pragma unroll
        for (int c2 = 0; c2 < 4; c2++) {
            ulonglong2 bm = BmH2[c2 * 256 + m];
            acc9[2 * c2]     = mul2p(acc9[2 * c2], bm.x);
            acc9[2 * c2 + 1] = mul2p(acc9[2 * c2 + 1], bm.y);
            u64 pr = add2p(acc9[2 * c2], acc9[2 * c2 + 1]);
            nu = (c2 == 0) ? pr : add2p(nu, pr);
        }
        nuprodU = mul2p(nuprodU, nu);
        float nx, ny; unpk2f(nu, nx, ny);
        u64 r = pk2f(__fdividef(1.f, nx), __fdividef(1.f, ny));
#pragma unroll
        for (int c = 0; c < 8; c++) acc9[c] = mul2p(acc9[c], r);
        u64 msg[8];
        matvec8p(A2h + p9 * 2, acc9, msg, false);
#pragma unroll
        for (int c = 0; c < 8; c++) bufAh[c * 512 + nd] = msg[c];

        float ax, ay, bx, by;
        unpk2f(llleaf, ax, ay);
        unpk2f(nuprodU, bx, by);
        llx += ax + __logf(bx);
        lly += ay + __logf(by);
    }
    __syncthreads();

    // ---- single-phase levels: l = child level (9,8,7); logs batched ----
    {
        float prodx = 1.f, prody = 1.f;
#pragma unroll 1
        for (int l = 9; l >= 7; --l) {
            const int n_pa = 1 << (l - 1);            // 256, 128, 64
            u64* chb = (l & 1) ? bufAh : bufBh;
            const int csh = (l & 1) ? 256 : 128;
            u64* pb  = (l & 1) ? bufBh : bufAh;
            const int ps2 = (l & 1) ? 256 : 512;
            const int hb = (1 << (l - 1)) - 1;        // heap base of level l-1

            if (nd < n_pa) {
                const int pa = nd;
                int m = xs[hb + pa];
                int p = ps[hb + pa];
                const ulonglong2* ch2 = (const ulonglong2*)chb;
                u64 v[8];
                u64 nu;
#pragma unroll
                for (int c2 = 0; c2 < 4; c2++) {
                    ulonglong2 prA = ch2[(2 * c2) * csh + pa];
                    ulonglong2 prB = ch2[(2 * c2 + 1) * csh + pa];
                    ulonglong2 bm = BmH2[c2 * 256 + m];
                    v[2 * c2]     = mul2p(add2p(prA.x, prA.y), bm.x);
                    v[2 * c2 + 1] = mul2p(add2p(prB.x, prB.y), bm.y);
                    u64 pr = add2p(v[2 * c2], v[2 * c2 + 1]);
                    nu = (c2 == 0) ? pr : add2p(nu, pr);
                }
                float nx, ny; unpk2f(nu, nx, ny);
                prodx *= nx; prody *= ny;
                u64 r = pk2f(__fdividef(1.f, nx), __fdividef(1.f, ny));
#pragma unroll
                for (int c = 0; c < 8; c++) v[c] = mul2p(v[c], r);
                u64 msg[8];
                matvec8p(A2h + p * 2, v, msg, false);
#pragma unroll
                for (int c = 0; c < 8; c++) pb[c * ps2 + pa] = msg[c];
            }
            __syncthreads();
        }
        if (nd < 256) {
            llx += __logf(prodx);
            lly += __logf(prody);
        }
    }

    // ---- tail: l = 6..1, two independent warps (one per gh), smem x/pos ----
    if (nd < 32) {
        float prodx = 1.f, prody = 1.f;
#pragma unroll 1
        for (int l = 6; l >= 1; --l) {
            const int n_pa = 1 << (l - 1);
            u64* chb = (l & 1) ? bufAh : bufBh;
            const int csh = (l & 1) ? 256 : 128;
            u64* pb  = (l & 1) ? bufBh : bufAh;
            const int ps2 = (l & 1) ? 256 : 512;
            const int hb = (1 << (l - 1)) - 1;

            if (nd < n_pa) {
                const int pa = nd;
                int m = xs[hb + pa];
                const ulonglong2* ch2 = (const ulonglong2*)chb;
                u64 v[8];
                u64 nu;
#pragma unroll
                for (int c2 = 0; c2 < 4; c2++) {
                    ulonglong2 prA = ch2[(2 * c2) * csh + pa];
                    ulonglong2 prB = ch2[(2 * c2 + 1) * csh + pa];
                    ulonglong2 bm = BmH2[c2 * 256 + m];
                    v[2 * c2]     = mul2p(add2p(prA.x, prA.y), bm.x);
                    v[2 * c2 + 1] = mul2p(add2p(prB.x, prB.y), bm.y);
                    u64 pr = add2p(v[2 * c2], v[2 * c2 + 1]);
                    nu = (c2 == 0) ? pr : add2p(nu, pr);
                }
                float nx, ny; unpk2f(nu, nx, ny);
                prodx *= nx; prody *= ny;
                if (l > 1) {
                    int p = ps[hb + pa];
                    u64 r = pk2f(__fdividef(1.f, nx), __fdividef(1.f, ny));
#pragma unroll
                    for (int c = 0; c < 8; c++) v[c] = mul2p(v[c], r);
                    u64 msg[8];
                    matvec8p(A2h + p * 2, v, msg, false);
#pragma unroll
                    for (int c = 0; c < 8; c++) pb[c * ps2 + pa] = msg[c];
                }
            }
            __syncwarp();
        }
        llx += __logf(prodx);
        lly += __logf(prody);
    }

    // ---- reduction ----
#pragma unroll
    for (int o = 16; o; o >>= 1) {
        llx += __shfl_xor_sync(0xffffffffu, llx, o);
        lly += __shfl_xor_sync(0xffffffffu, lly, o);
    }
    if ((tid & 31) == 0) {
        atomicAdd(&red[2 * gh + 0], llx);
        atomicAdd(&red[2 * gh + 1], lly);
    }
    __syncthreads();
    if (tid < 4) out[t * 4 + tid] = red[tid];
}

extern "C" void kernel_launch(void* const* d_in, const int* in_sizes, int n_in,
                              void* d_out, int out_size) {
    const float* lA  = (const float*)d_in[0];
    const float* lB  = (const float*)d_in[1];
    const float* lPi = (const float*)d_in[2];
    const float* lSP = (const float*)d_in[3];
    const int*   pos = (const int*)d_in[4];
    const int*   x   = (const int*)d_in[5];
    float*       out = (float*)d_out;

    cudaFuncSetAttribute(htmm_main, cudaFuncAttributeMaxDynamicSharedMemorySize, SMEM_BYTES);

    htmm_main<<<NTREES, NTH, SMEM_BYTES>>>(lA, lB, lPi, lSP, pos, x, out);
}

// round 15
// speedup vs baseline: 1.1578x; 1.0142x over previous
#include <cuda_runtime.h>

#define NTREES 128
#define C 8
#define L 2
#define M 256
#define G 4
#define NTH 1024

typedef unsigned long long u64;

// ---------------- packed f32x2 helpers ----------------
static __device__ __forceinline__ u64 pk2f(float lo, float hi) {
    u64 r; asm("mov.b64 %0,{%1,%2};" : "=l"(r) : "f"(lo), "f"(hi)); return r;
}
static __device__ __forceinline__ void unpk2f(u64 v, float& lo, float& hi) {
    asm("mov.b64 {%0,%1},%2;" : "=f"(lo), "=f"(hi) : "l"(v));
}
static __device__ __forceinline__ u64 fma2p(u64 a, u64 b, u64 c) {
    u64 d; asm("fma.rn.f32x2 %0,%1,%2,%3;" : "=l"(d) : "l"(a), "l"(b), "l"(c)); return d;
}
static __device__ __forceinline__ u64 mul2p(u64 a, u64 b) {
    u64 d; asm("mul.rn.f32x2 %0,%1,%2;" : "=l"(d) : "l"(a), "l"(b)); return d;
}
static __device__ __forceinline__ u64 add2p(u64 a, u64 b) {
    u64 d; asm("add.rn.f32x2 %0,%1,%2;" : "=l"(d) : "l"(a), "l"(b)); return d;
}
// bf16x2 (u32) -> f32x2 (u64): bf16 is truncated fp32, so just shift/mask.
static __device__ __forceinline__ u64 bf2f(unsigned v) {
    unsigned lo = v << 16, hi = v & 0xffff0000u;
    u64 r; asm("mov.b64 %0,{%1,%2};" : "=l"(r) : "r"(lo), "r"(hi)); return r;
}
// two f32 -> bf16x2 (u32), round-to-nearest; lo -> bits[15:0]
static __device__ __forceinline__ unsigned f2bf2(float lo, float hi) {
    unsigned r; asm("cvt.rn.bf16x2.f32 %0,%1,%2;" : "=r"(r) : "f"(hi), "f"(lo)); return r;
}
static __device__ __forceinline__ unsigned short f2bf1(float f) {
    unsigned short h; asm("cvt.rn.bf16.f32 %0,%1;" : "=h"(h) : "f"(f)); return h;
}

// 8x8 matvec: A as ulonglong2 pairs over d; Ap pre-offset by (p*2 + gh).
static __device__ __forceinline__ void matvec8p(const ulonglong2* __restrict__ Ap,
                                                const u64* __restrict__ b,
                                                u64* __restrict__ o, bool acc) {
#pragma unroll
    for (int c = 0; c < 8; c++) {
        u64 mm = acc ? o[c] : 0ull;
#pragma unroll
        for (int d2 = 0; d2 < 4; d2++) {
            ulonglong2 a = Ap[(c * 4 + d2) * 4];
            mm = fma2p(a.x, b[2 * d2], mm);
            mm = fma2p(a.y, b[2 * d2 + 1], mm);
        }
        o[c] = mm;
    }
}

// ---------------- single fused kernel: one CTA per tree ----------------
// smem map (u64 units):
//   bufA  [0, 8192)       : [gh][c][512]  fp32 pairs (levels 9,7,5,3,1)
//   bufB  [8192, 12288)   : [gh][c][256]  fp32 pairs (levels 8,6,4,2)
//   BmB   [12288, 14336)  : bf16x2 [gh][m][8c]  (32B per (gh,m) = 2x ull2)
//   A_s   [14336, 14592)  : fp32 ulonglong2[c][d2][p][gh]
//   TmsgB [14592, 18688)  : bf16x2 [gh][pm][8c] (32B per (gh,pm) = 2x ull2)
//   Tlog  [18688, 19712)  : fp32 pairs [gh][pm]
//   Pi_s  [19712, 19744)  : fp32 pairs [p][c][gh]
//   red   [19744, 19746)  : 4 floats
//   xs    [19746, 20258)  : 1024 ints (heap order, levels 0..9)
//   ps    [20258, 20770)  : 1024 ints
#define SMEM_U64 20770
#define SMEM_BYTES (SMEM_U64 * 8)

__global__ __launch_bounds__(NTH) void htmm_main(const float* __restrict__ lA,
                                                 const float* __restrict__ lB,
                                                 const float* __restrict__ lPi,
                                                 const float* __restrict__ lSP,
                                                 const int* __restrict__ pos,
                                                 const int* __restrict__ x,
                                                 float* __restrict__ out) {
    extern __shared__ u64 smu[];
    float* red = (float*)(smu + 19744);
    int* xs = (int*)(smu + 19746);
    int* ps = (int*)(smu + 20258);

    const int t = blockIdx.x, tid = threadIdx.x;
    const int gh = tid >> 9, nd = tid & 511;
    const int wid = tid >> 5, lane = tid & 31;

    // ========== prefetch x/pos for levels 0..9 into smem (heap order) ==========
    if (tid < 1023) {
        int ip1 = tid + 1;
        int l = 31 - __clz(ip1);
        int j = ip1 - (1 << l);
        int gidx = 128 * ((1 << l) - 1) + (t << l) + j;
        xs[tid] = x[gidx];
        ps[tid] = pos[gidx];
    }

    // ========== per-CTA prologue 1: softmaxes into smem ==========
    // Bm: one warp per (c,g); bf16 store into [gh][m][c*2+gl] u16 layout.
    {
        int c = wid >> 2, g = wid & 3;
        float v[8];
        float mx = -1e30f;
#pragma unroll
        for (int j = 0; j < 8; j++) {
            v[j] = lB[(c * M + lane + 32 * j) * G + g];
            mx = fmaxf(mx, v[j]);
        }
#pragma unroll
        for (int o = 16; o; o >>= 1) mx = fmaxf(mx, __shfl_xor_sync(0xffffffffu, mx, o));
        float s = 0.f;
#pragma unroll
        for (int j = 0; j < 8; j++) { v[j] = __expf(v[j] - mx); s += v[j]; }
#pragma unroll
        for (int o = 16; o; o >>= 1) s += __shfl_xor_sync(0xffffffffu, s, o);
        float r = 1.f / s;
        unsigned short* bm16 = (unsigned short*)(smu + 12288);
        int ghw = g >> 1, gl = g & 1;
#pragma unroll
        for (int j = 0; j < 8; j++) {
            int m = lane + 32 * j;
            bm16[ghw * 4096 + m * 16 + c * 2 + gl] = f2bf1(v[j] * r);
        }
    }
    if (tid < 64) {
        int d = tid >> 3, p = (tid >> 2) & 1, g = tid & 3;
        float s0 = lSP[0 * G + g], s1 = lSP[1 * G + g];
        float mxs = fmaxf(s0, s1);
        float e0 = __expf(s0 - mxs), e1 = __expf(s1 - mxs);
        float sp = (p == 0 ? e0 : e1) / (e0 + e1);
        float mx = -1e30f;
#pragma unroll
        for (int c = 0; c < C; c++) mx = fmaxf(mx, lA[((c * C + d) * L + p) * G + g]);
        float s = 0.f;
#pragma unroll
        for (int c = 0; c < C; c++) s += __expf(lA[((c * C + d) * L + p) * G + g] - mx);
        float r = sp / s;
        float* AF = (float*)(smu + 14336);
        int d2 = d >> 1, dl = d & 1, ghx = g >> 1, gl = g & 1;
#pragma unroll
        for (int c = 0; c < C; c++) {
            int fi = ((((c * 4 + d2) * 2 + p) * 2 + ghx) * 2 + dl) * 2 + gl;
            AF[fi] = __expf(lA[((c * C + d) * L + p) * G + g] - mx) * r;
        }
    } else if (tid < 72) {
        int t2 = tid - 64;
        int p = t2 >> 2, g = t2 & 3;
        float mx = -1e30f;
#pragma unroll
        for (int c = 0; c < C; c++) mx = fmaxf(mx, lPi[(c * L + p) * G + g]);
        float s = 0.f;
#pragma unroll
        for (int c = 0; c < C; c++) s += __expf(lPi[(c * L + p) * G + g] - mx);
        float r = 1.f / s;
        float* PiF = (float*)(smu + 19712);  // idx p*32 + c*4 + g
#pragma unroll
        for (int c = 0; c < C; c++)
            PiF[p * 32 + c * 4 + g] = __expf(lPi[(c * L + p) * G + g] - mx) * r;
    }
    if (tid < 4) red[tid] = 0.f;
    __syncthreads();

    const ulonglong2* A2 = (const ulonglong2*)(smu + 14336);  // [(c*4+d2)*4 + p*2 + gh]

    // ========== per-CTA prologue 2: leaf table (thread = (pm, gh)) ==========
    {
        const int pm = tid & 511, ghb = tid >> 9;
        const int p = pm >> 8, m = pm & 255;
        const ulonglong2* BmB2G = (const ulonglong2*)(smu + 12288) + ghb * 512;
        u64 b[8], nu;
#pragma unroll
        for (int k = 0; k < 2; k++) {
            ulonglong2 w = BmB2G[m * 2 + k];
            b[k * 4 + 0] = bf2f((unsigned)w.x);
            b[k * 4 + 1] = bf2f((unsigned)(w.x >> 32));
            b[k * 4 + 2] = bf2f((unsigned)w.y);
            b[k * 4 + 3] = bf2f((unsigned)(w.y >> 32));
        }
#pragma unroll
        for (int c = 0; c < 8; c++) {
            b[c] = mul2p(smu[19712 + p * 16 + c * 2 + ghb], b[c]);
            nu = (c == 0) ? b[0] : add2p(nu, b[c]);
        }
        float nx, ny; unpk2f(nu, nx, ny);
        smu[18688 + ghb * 512 + pm] = pk2f(__logf(nx), __logf(ny));
        u64 r = pk2f(__fdividef(1.f, nx), __fdividef(1.f, ny));
#pragma unroll
        for (int c = 0; c < 8; c++) b[c] = mul2p(b[c], r);
        u64 msg[8];
        matvec8p(A2 + p * 2 + ghb, b, msg, false);
        unsigned* TB32 = (unsigned*)(smu + 14592);
#pragma unroll
        for (int c = 0; c < 8; c++) {
            float lo, hi; unpk2f(msg[c], lo, hi);
            TB32[(ghb * 512 + pm) * 8 + c] = f2bf2(lo, hi);
        }
    }
    __syncthreads();

    const ulonglong2* BmB2h = (const ulonglong2*)(smu + 12288) + gh * 512;   // [m*2+k]
    const ulonglong2* TB2h  = (const ulonglong2*)(smu + 14592) + gh * 1024;  // [pm*2+k]
    const u64* TlogH = smu + 18688 + gh * 512;
    const ulonglong2* A2h = A2 + gh;
    u64* bufAh = smu + gh * 4096;
    u64* bufBh = smu + 8192 + gh * 2048;

    float llx = 0.f, lly = 0.f;

    // ---- fused levels 11 (table lookup) -> 10 -> 9 in registers ----
    {
        const int offL  = 128 * 2047 + (t << 11);
        const int off10 = 128 * 1023 + (t << 10);

        const int4 pL  = *(const int4*)(pos + offL + 4 * nd);
        const int4 xL  = *(const int4*)(x   + offL + 4 * nd);
        const int2 p10 = *(const int2*)(pos + off10 + 2 * nd);
        const int2 x10 = *(const int2*)(x   + off10 + 2 * nd);

        const int pm0 = pL.x * 256 + xL.x, pm1 = pL.y * 256 + xL.y;
        const int pm2 = pL.z * 256 + xL.z, pm3 = pL.w * 256 + xL.w;

        u64 llleaf = add2p(add2p(TlogH[pm0], TlogH[pm1]), add2p(TlogH[pm2], TlogH[pm3]));

        u64 acc9[8];
        u64 nuprodU = pk2f(1.f, 1.f);

#pragma unroll
        for (int s10 = 0; s10 < 2; s10++) {
            const int pma = (s10 == 0) ? pm0 : pm2;
            const int pmb = (s10 == 0) ? pm1 : pm3;
            int m = (s10 == 0) ? x10.x : x10.y;
            int p = (s10 == 0) ? p10.x : p10.y;

            u64 acc10[8];
            u64 nu;
#pragma unroll
            for (int k = 0; k < 2; k++) {
                ulonglong2 wa = TB2h[pma * 2 + k];
                ulonglong2 wb = TB2h[pmb * 2 + k];
                ulonglong2 wm = BmB2h[m * 2 + k];
                unsigned qa[4] = {(unsigned)wa.x, (unsigned)(wa.x >> 32),
                                  (unsigned)wa.y, (unsigned)(wa.y >> 32)};
                unsigned qb[4] = {(unsigned)wb.x, (unsigned)(wb.x >> 32),
                                  (unsigned)wb.y, (unsigned)(wb.y >> 32)};
                unsigned qm[4] = {(unsigned)wm.x, (unsigned)(wm.x >> 32),
                                  (unsigned)wm.y, (unsigned)(wm.y >> 32)};
#pragma unroll
                for (int j = 0; j < 4; j++) {
                    int c = k * 4 + j;
                    acc10[c] = mul2p(add2p(bf2f(qa[j]), bf2f(qb[j])), bf2f(qm[j]));
                    nu = (c == 0) ? acc10[0] : add2p(nu, acc10[c]);
                }
            }
            nuprodU = mul2p(nuprodU, nu);
            float nx, ny; unpk2f(nu, nx, ny);
            u64 r = pk2f(__fdividef(1.f, nx), __fdividef(1.f, ny));
#pragma unroll
            for (int c = 0; c < 8; c++) acc10[c] = mul2p(acc10[c], r);
            matvec8p(A2h + p * 2, acc10, acc9, s10 != 0);
        }
        // level-9 node (x/pos from prefetched smem: heap index 511+nd)
        int m = xs[511 + nd];
        int p9 = ps[511 + nd];
        u64 nu;
#pragma unroll
        for (int k = 0; k < 2; k++) {
            ulonglong2 wm = BmB2h[m * 2 + k];
            unsigned qm[4] = {(unsigned)wm.x, (unsigned)(wm.x >> 32),
                              (unsigned)wm.y, (unsigned)(wm.y >> 32)};
#pragma unroll
            for (int j = 0; j < 4; j++) {
                int c = k * 4 + j;
                acc9[c] = mul2p(acc9[c], bf2f(qm[j]));
                nu = (c == 0) ? acc9[0] : add2p(nu, acc9[c]);
            }
        }
        nuprodU = mul2p(nuprodU, nu);
        float nx, ny; unpk2f(nu, nx, ny);
        u64 r = pk2f(__fdividef(1.f, nx), __fdividef(1.f, ny));
#pragma unroll
        for (int c = 0; c < 8; c++) acc9[c] = mul2p(acc9[c], r);
        u64 msg[8];
        matvec8p(A2h + p9 * 2, acc9, msg, false);
#pragma unroll
        for (int c = 0; c < 8; c++) bufAh[c * 512 + nd] = msg[c];

        float ax, ay, bx, by;
        unpk2f(llleaf, ax, ay);
        unpk2f(nuprodU, bx, by);
        llx += ax + __logf(bx);
        lly += ay + __logf(by);
    }
    __syncthreads();

    // ---- single-phase levels: l = child level (9,8,7); logs batched ----
    {
        float prodx = 1.f, prody = 1.f;
#pragma unroll 1
        for (int l = 9; l >= 7; --l) {
            const int n_pa = 1 << (l - 1);            // 256, 128, 64
            u64* chb = (l & 1) ? bufAh : bufBh;
            const int csh = (l & 1) ? 256 : 128;
            u64* pb  = (l & 1) ? bufBh : bufAh;
            const int ps2 = (l & 1) ? 256 : 512;
            const int hb = (1 << (l - 1)) - 1;        // heap base of level l-1

            if (nd < n_pa) {
                const int pa = nd;
                int m = xs[hb + pa];
                int p = ps[hb + pa];
                const ulonglong2* ch2 = (const ulonglong2*)chb;
                u64 v[8];
                u64 nu;
#pragma unroll
                for (int k = 0; k < 2; k++) {
                    ulonglong2 wm = BmB2h[m * 2 + k];
                    unsigned qm[4] = {(unsigned)wm.x, (unsigned)(wm.x >> 32),
                                      (unsigned)wm.y, (unsigned)(wm.y >> 32)};
#pragma unroll
                    for (int j = 0; j < 4; j++) {
                        int c = k * 4 + j;
                        ulonglong2 pr = ch2[c * csh + pa];
                        v[c] = mul2p(add2p(pr.x, pr.y), bf2f(qm[j]));
                        nu = (c == 0) ? v[0] : add2p(nu, v[c]);
                    }
                }
                float nx, ny; unpk2f(nu, nx, ny);
                prodx *= nx; prody *= ny;
                u64 r = pk2f(__fdividef(1.f, nx), __fdividef(1.f, ny));
#pragma unroll
                for (int c = 0; c < 8; c++) v[c] = mul2p(v[c], r);
                u64 msg[8];
                matvec8p(A2h + p * 2, v, msg, false);
#pragma unroll
                for (int c = 0; c < 8; c++) pb[c * ps2 + pa] = msg[c];
            }
            __syncthreads();
        }
        if (nd < 256) {
            llx += __logf(prodx);
            lly += __logf(prody);
        }
    }

    // ---- tail: l = 6..1, two independent warps (one per gh), smem x/pos ----
    if (nd < 32) {
        float prodx = 1.f, prody = 1.f;
#pragma unroll 1
        for (int l = 6; l >= 1; --l) {
            const int n_pa = 1 << (l - 1);
            u64* chb = (l & 1) ? bufAh : bufBh;
            const int csh = (l & 1) ? 256 : 128;
            u64* pb  = (l & 1) ? bufBh : bufAh;
            const int ps2 = (l & 1) ? 256 : 512;
            const int hb = (1 << (l - 1)) - 1;

            if (nd < n_pa) {
                const int pa = nd;
                int m = xs[hb + pa];
                const ulonglong2* ch2 = (const ulonglong2*)chb;
                u64 v[8];
                u64 nu;
#pragma unroll
                for (int k = 0; k < 2; k++) {
                    ulonglong2 wm = BmB2h[m * 2 + k];
                    unsigned qm[4] = {(unsigned)wm.x, (unsigned)(wm.x >> 32),
                                      (unsigned)wm.y, (unsigned)(wm.y >> 32)};
#pragma unroll
                    for (int j = 0; j < 4; j++) {
                        int c = k * 4 + j;
                        ulonglong2 pr = ch2[c * csh + pa];
                        v[c] = mul2p(add2p(pr.x, pr.y), bf2f(qm[j]));
                        nu = (c == 0) ? v[0] : add2p(nu, v[c]);
                    }
                }
                float nx, ny; unpk2f(nu, nx, ny);
                prodx *= nx; prody *= ny;
                if (l > 1) {
                    int p = ps[hb + pa];
                    u64 r = pk2f(__fdividef(1.f, nx), __fdividef(1.f, ny));
#pragma unroll
                    for (int c = 0; c < 8; c++) v[c] = mul2p(v[c], r);
                    u64 msg[8];
                    matvec8p(A2h + p * 2, v, msg, false);
#pragma unroll
                    for (int c = 0; c < 8; c++) pb[c * ps2 + pa] = msg[c];
                }
            }
            __syncwarp();
        }
        llx += __logf(prodx);
        lly += __logf(prody);
    }

    // ---- reduction ----
#pragma unroll
    for (int o = 16; o; o >>= 1) {
        llx += __shfl_xor_sync(0xffffffffu, llx, o);
        lly += __shfl_xor_sync(0xffffffffu, lly, o);
    }
    if ((tid & 31) == 0) {
        atomicAdd(&red[2 * gh + 0], llx);
        atomicAdd(&red[2 * gh + 1], lly);
    }
    __syncthreads();
    if (tid < 4) out[t * 4 + tid] = red[tid];
}

extern "C" void kernel_launch(void* const* d_in, const int* in_sizes, int n_in,
                              void* d_out, int out_size) {
    const float* lA  = (const float*)d_in[0];
    const float* lB  = (const float*)d_in[1];
    const float* lPi = (const float*)d_in[2];
    const float* lSP = (const float*)d_in[3];
    const int*   pos = (const int*)d_in[4];
    const int*   x   = (const int*)d_in[5];
    float*       out = (float*)d_out;

    cudaFuncSetAttribute(htmm_main, cudaFuncAttributeMaxDynamicSharedMemorySize, SMEM_BYTES);

    htmm_main<<<NTREES, NTH, SMEM_BYTES>>>(lA, lB, lPi, lSP, pos, x, out);
}